// round 1
// baseline (speedup 1.0000x reference)
#include <cuda_runtime.h>
#include <cuda_bf16.h>

// Problem constants
#define OUT_NUM 1024
#define LUT_NUM 64
#define LUT_K   6
#define BR      32                 // 16 batch * 2
#define FEAT    (LUT_NUM * LUT_K)  // 384

// y(b,r,out,lut) = sum_j wq[j] * prod_l ( bit_l if ((j>>l)&1) else (1-bit_l) )
// wq = (tanh(w)+1)/2 = sigmoid(2w), evaluated via fast exp + fast divide
// (abs error ~1e-6, far under the 1e-3 gate; tanh.approx would be ~5e-4, too risky).
//
// Thread = one (out, lut). base[32] + d[32] (level-0 table halves & diffs) live in
// registers and are reused across all 32 (b,r) slices, turning level 0 into a
// single FFMA per node (94 flops/output instead of 126).

__global__ __launch_bounds__(64)
void lut_tree_kernel(const float* __restrict__ x,
                     const float* __restrict__ w,
                     float* __restrict__ out)
{
    const int lut = threadIdx.x;      // 0..63
    const int o   = blockIdx.x;       // 0..1023

    // ---- load w row (64 consecutive floats, 256B-aligned), build wq, base, d ----
    const float4* wp =
        reinterpret_cast<const float4*>(w + (((size_t)o * LUT_NUM + lut) << 6));

    float base[32], d[32];
#pragma unroll
    for (int i = 0; i < 16; ++i) {
        float4 v = wp[i];
        // sigmoid(2w) == (tanh(w)+1)/2
        float s0 = __fdividef(1.0f, 1.0f + __expf(-2.0f * v.x));
        float s1 = __fdividef(1.0f, 1.0f + __expf(-2.0f * v.y));
        float s2 = __fdividef(1.0f, 1.0f + __expf(-2.0f * v.z));
        float s3 = __fdividef(1.0f, 1.0f + __expf(-2.0f * v.w));
        base[2 * i]     = s0;  d[2 * i]     = s1 - s0;
        base[2 * i + 1] = s2;  d[2 * i + 1] = s3 - s2;
    }

    // ---- per-(b,r) tree evaluation ----
    // x bit address: ((br*1024 + o)*384 + lut*6 + l); lut*6 floats -> 8B aligned.
    const float* xp = x + (size_t)o * FEAT + lut * LUT_K;
    float*       op = out + (size_t)o * LUT_NUM + lut;

    for (int br = 0; br < BR; ++br) {          // NOT unrolled: keep body in L0 I$
        const float* xb = xp + (size_t)br * ((size_t)OUT_NUM * FEAT);
        float2 b01 = *reinterpret_cast<const float2*>(xb);
        float2 b23 = *reinterpret_cast<const float2*>(xb + 2);
        float2 b45 = *reinterpret_cast<const float2*>(xb + 4);

        float y[32];
        // level 0: y_i = base_i + bit0 * d_i      (32 independent FFMAs)
#pragma unroll
        for (int i = 0; i < 32; ++i) y[i] = fmaf(b01.x, d[i], base[i]);
        // levels 1..5: y_i = y_{2i} + bit_l * (y_{2i+1} - y_{2i})
#pragma unroll
        for (int i = 0; i < 16; ++i) y[i] = fmaf(b01.y, y[2 * i + 1] - y[2 * i], y[2 * i]);
#pragma unroll
        for (int i = 0; i < 8; ++i)  y[i] = fmaf(b23.x, y[2 * i + 1] - y[2 * i], y[2 * i]);
#pragma unroll
        for (int i = 0; i < 4; ++i)  y[i] = fmaf(b23.y, y[2 * i + 1] - y[2 * i], y[2 * i]);
#pragma unroll
        for (int i = 0; i < 2; ++i)  y[i] = fmaf(b45.x, y[2 * i + 1] - y[2 * i], y[2 * i]);
        float r = fmaf(b45.y, y[1] - y[0], y[0]);

        op[(size_t)br * ((size_t)OUT_NUM * LUT_NUM)] = r;
    }
}

extern "C" void kernel_launch(void* const* d_in, const int* in_sizes, int n_in,
                              void* d_out, int out_size)
{
    const float* x = (const float*)d_in[0];
    const float* w = (const float*)d_in[1];
    // Hedge against input-order surprises: x (12.6M elems) is larger than w (4.2M).
    if (n_in >= 2 && in_sizes[0] < in_sizes[1]) {
        const float* t = x; x = w; w = t;
    }
    float* out = (float*)d_out;

    lut_tree_kernel<<<OUT_NUM, 64>>>(x, w, out);
}

// round 2
// speedup vs baseline: 1.1235x; 1.1235x over previous
#include <cuda_runtime.h>
#include <cuda_bf16.h>

// Problem constants
#define OUT_NUM 1024
#define LUT_NUM 64
#define LUT_K   6
#define BR      32                 // 16 batch * 2
#define FEAT    (LUT_NUM * LUT_K)  // 384

// y(b,r,out,lut) = 6-level binary-tree lerp over wq = sigmoid(2w).
//
// R2 layout: each (out,lut) table is SPLIT across a thread pair on tree bit5.
// Thread half h owns w entries [32h, 32h+32): base[16] + d[16] in registers,
// evaluates the 5-level subtree (bits 0..4), then the pair combines via one
// __shfl_xor + FFMA on bit5. Doubles the warp pool (2048 -> 4096 warps) that
// R1's ncu showed was the bottleneck (occ 19.5%, issue 27.9%), with no extra
// sigmoid work and unchanged, fully-coalesced w loads.

__global__ __launch_bounds__(128, 7)
void lut_tree_kernel(const float* __restrict__ x,
                     const float* __restrict__ w,
                     float* __restrict__ out)
{
    const int tid  = threadIdx.x;       // 0..127
    const int lut  = tid >> 1;          // 0..63
    const int half = tid & 1;           // tree bit5
    const int o    = blockIdx.x;        // 0..1023

    // ---- load my 32 contiguous w floats (128B per thread, warp fully coalesced) ----
    const float4* wp = reinterpret_cast<const float4*>(
        w + (((size_t)o * LUT_NUM + lut) << 6) + (half << 5));

    float base[16], d[16];
#pragma unroll
    for (int i = 0; i < 8; ++i) {
        float4 v = wp[i];
        // sigmoid(2w) == (tanh(w)+1)/2 ; abs err ~1e-6 << 1e-3 gate
        float s0 = __fdividef(1.0f, 1.0f + __expf(-2.0f * v.x));
        float s1 = __fdividef(1.0f, 1.0f + __expf(-2.0f * v.y));
        float s2 = __fdividef(1.0f, 1.0f + __expf(-2.0f * v.z));
        float s3 = __fdividef(1.0f, 1.0f + __expf(-2.0f * v.w));
        base[2 * i]     = s0;  d[2 * i]     = s1 - s0;
        base[2 * i + 1] = s2;  d[2 * i + 1] = s3 - s2;
    }

    // ---- per-(b,r) tree evaluation ----
    // x bits: x[br, o, lut*6 .. +6); 8B-aligned (o*384*4 and lut*24 both %8==0)
    const float* xp = x + (size_t)o * FEAT + lut * LUT_K;
    float*       op = out + (size_t)o * LUT_NUM + lut;

    for (int br = 0; br < BR; ++br) {          // NOT unrolled: keep body in L0 I$
        const float* xb = xp + (size_t)br * ((size_t)OUT_NUM * FEAT);
        float2 b01 = *reinterpret_cast<const float2*>(xb);       // bits 0,1
        float2 b23 = *reinterpret_cast<const float2*>(xb + 2);   // bits 2,3
        float2 b45 = *reinterpret_cast<const float2*>(xb + 4);   // bits 4,5

        float y[16];
        // level 0 (bit0): y_i = base_i + b0 * d_i
#pragma unroll
        for (int i = 0; i < 16; ++i) y[i] = fmaf(b01.x, d[i], base[i]);
        // levels 1..4
#pragma unroll
        for (int i = 0; i < 8; ++i)  y[i] = fmaf(b01.y, y[2 * i + 1] - y[2 * i], y[2 * i]);
#pragma unroll
        for (int i = 0; i < 4; ++i)  y[i] = fmaf(b23.x, y[2 * i + 1] - y[2 * i], y[2 * i]);
#pragma unroll
        for (int i = 0; i < 2; ++i)  y[i] = fmaf(b23.y, y[2 * i + 1] - y[2 * i], y[2 * i]);
        float v = fmaf(b45.x, y[1] - y[0], y[0]);   // my subtree value (bit4 applied)

        // level 5 (bit5): combine pair via shuffle
        float v_other = __shfl_xor_sync(0xFFFFFFFFu, v, 1);
        float lo = half ? v_other : v;
        float hi = half ? v : v_other;
        float r  = fmaf(b45.y, hi - lo, lo);

        if (half == 0)
            op[(size_t)br * ((size_t)OUT_NUM * LUT_NUM)] = r;
    }
}

extern "C" void kernel_launch(void* const* d_in, const int* in_sizes, int n_in,
                              void* d_out, int out_size)
{
    const float* x = (const float*)d_in[0];
    const float* w = (const float*)d_in[1];
    if (n_in >= 2 && in_sizes[0] < in_sizes[1]) {   // hedge on input order
        const float* t = x; x = w; w = t;
    }
    float* out = (float*)d_out;

    lut_tree_kernel<<<OUT_NUM, 128>>>(x, w, out);
}